// round 16
// baseline (speedup 1.0000x reference)
#include <cuda_runtime.h>
#include <math.h>

// ---------------- problem constants ----------------
#define BB   8
#define NN   2048
#define MM   2048
#define GG   544          // NUM_GRID
#define RC   8            // RHO_C
#define SC   1024         // SIGMA_CH
#define XMINF (-2.1f)
#define STEPF ((float)(4.2 / 543.0))
#define CUT_T 25.0f       // exp threshold: drop terms below e^-25 of peak

// ---------------- scratch (device globals) ----------------
__device__ float g_h[BB * GG * RC];          // h: [b][g][c]
__device__ float g_P[BB * MM * RC];          // ps[b,m,c]
__device__ float g_Q[BB * MM * RC];          // (G @ ps)[b,m,c]
__device__ float g_u[BB * MM];               // ps . (W b) + s/2
__device__ float g_G[RC * RC];               // sig_W sig_W^T
__device__ float g_wb[RC];                   // sig_W @ sig_b
__device__ float g_s[1];                     // sig_b . sig_b

// ---------------- packed f32x2 helpers (Blackwell) ----------------
#define FMA_F32X2(d, a, b, c) \
    asm("fma.rn.f32x2 %0, %1, %2, %3;" : "=l"(d) : "l"(a), "l"(b), "l"(c))
#define UNPACK_F32X2(lo, hi, v) \
    asm("mov.b64 {%0, %1}, %2;" : "=f"(lo), "=f"(hi) : "l"(v))
#define PACK_F32X2(out, lo, hi) \
    asm("mov.b64 %0, {%1, %2};" : "=l"(out) : "f"(lo), "f"(hi))

// window half-width in grid cells for gaussian coef magnitude
__device__ __forceinline__ int windowW(float negc)
{
    float dxmax = sqrtf(CUT_T / fmaxf(negc, 1e-30f));
    float wf = dxmax / STEPF + 2.0f;
    return (wf > (float)GG) ? GG : (int)wf;
}

// =====================================================================
// Kernel A (fused): scatter-encode per batch (blocks 0..7) + gram (block 8).
// Each point scatters its gaussian window into smem F0/F1 accumulators;
// epilogue computes h = (sigmoid(F @ enc_W + b) @ rho_W + b) per cell.
// =====================================================================
__global__ void __launch_bounds__(544) encode_kernel(
    const float* __restrict__ x, const float* __restrict__ y,
    const float* __restrict__ enc_sigma, const float* __restrict__ enc_W,
    const float* __restrict__ enc_b, const float* __restrict__ rho_W,
    const float* __restrict__ rho_b,
    const float* __restrict__ sig_W, const float* __restrict__ sig_b)
{
    int tid = threadIdx.x;
    int warp = tid >> 5, lane = tid & 31;

    if (blockIdx.x == BB) {
        // ---- gram block: G = sig_W sig_W^T, wb = sig_W @ sig_b, s = b.b
        if (warp < 8) {
            for (int p = warp * 8; p < warp * 8 + 8; p++) {
                int i = p >> 3, j = p & 7;
                float acc = 0.f;
                for (int k = lane; k < SC; k += 32)
                    acc += sig_W[i * SC + k] * sig_W[j * SC + k];
                for (int off = 16; off; off >>= 1)
                    acc += __shfl_xor_sync(0xffffffffu, acc, off);
                if (lane == 0) g_G[p] = acc;
            }
            float acc = 0.f;
            for (int k = lane; k < SC; k += 32)
                acc += sig_W[warp * SC + k] * sig_b[k];
            for (int off = 16; off; off >>= 1)
                acc += __shfl_xor_sync(0xffffffffu, acc, off);
            if (lane == 0) g_wb[warp] = acc;
            if (warp == 0) {
                float a2 = 0.f;
                for (int k = lane; k < SC; k += 32)
                    a2 += sig_b[k] * sig_b[k];
                for (int off = 16; off; off >>= 1)
                    a2 += __shfl_xor_sync(0xffffffffu, a2, off);
                if (lane == 0) g_s[0] = a2;
            }
        }
        return;
    }

    int b = blockIdx.x;
    __shared__ float F0s[GG];
    __shared__ float F1s[GG];

    for (int i = tid; i < GG; i += 544) { F0s[i] = 0.f; F1s[i] = 0.f; }
    __syncthreads();

    float es0 = enc_sigma[0], es1 = enc_sigma[1];
    float s0 = __expf(es0);  float c0 = -0.5f / (s0 * s0);
    bool same = (es0 == es1);
    float c1 = c0;
    int W = windowW(-c0);
    if (!same) {
        float s1 = __expf(es1);
        c1 = -0.5f / (s1 * s1);
        W = max(W, windowW(-c1));
    }

    // scatter: each point adds to cells [cell-W, cell+W]
    for (int n = tid; n < NN; n += 544) {
        float xv = x[b * NN + n], yv = y[b * NN + n];
        float cf = (xv - XMINF) / STEPF + 0.5f;
        int cell = min(max((int)cf, 0), GG - 1);
        int wlo = max(0, cell - W), whi = min(GG - 1, cell + W);
        if (same) {
            for (int w = wlo; w <= whi; w++) {
                float dx = xv - (XMINF + (float)w * STEPF);
                float e = __expf(c0 * dx * dx);
                atomicAdd(&F0s[w], e);
                atomicAdd(&F1s[w], yv * e);
            }
        } else {
            for (int w = wlo; w <= whi; w++) {
                float dx = xv - (XMINF + (float)w * STEPF);
                float d = dx * dx;
                atomicAdd(&F0s[w], __expf(c0 * d));
                atomicAdd(&F1s[w], yv * __expf(c1 * d));
            }
        }
    }
    __syncthreads();

    // epilogue: one thread per grid cell
    if (tid < GG) {
        int g = tid;
        float F0 = F0s[g];
        float F1 = F1s[g] / (F0 + 1e-8f);

        float hh[RC];
        #pragma unroll
        for (int c = 0; c < RC; c++) {
            float z = F0 * enc_W[c] + F1 * enc_W[RC + c] + enc_b[c];
            hh[c] = 1.f / (1.f + __expf(-z));
        }
        #pragma unroll
        for (int c = 0; c < RC; c++) {
            float acc = rho_b[c];
            #pragma unroll
            for (int j = 0; j < RC; j++) acc += hh[j] * rho_W[j * RC + c];
            g_h[(b * GG + g) * RC + c] = acc;   // [b][g][c]
        }
    }
}

// =====================================================================
// Kernel C: project.  One 8-lane GROUP per (b,m); 64 m per block (512T).
// g_u gets +s/2 folded in (cov adds u[m]+u[n] -> +s total).
// =====================================================================
__global__ void __launch_bounds__(512) project_kernel(
    const float* __restrict__ x_out,
    const float* __restrict__ mean_sigma, const float* __restrict__ mean_W,
    const float* __restrict__ mean_b,
    const float* __restrict__ sig_sigma,
    float* __restrict__ mean_out)
{
    __shared__ __align__(16) float h_sh[GG * RC];    // [g][c]

    int b  = blockIdx.x >> 5;          // 32 blocks per batch
    int m0 = (blockIdx.x & 31) * 64;
    int tid = threadIdx.x;

    for (int i = tid; i < GG * RC; i += 512)
        h_sh[i] = g_h[b * GG * RC + i];
    __syncthreads();

    int gid   = tid >> 3;              // 0..63
    int lane8 = tid & 7;
    int m = m0 + gid;
    float xo = x_out[b * MM + m];

    bool uni = true;
    float ms0 = mean_sigma[0];
    float maxls = ms0;
    #pragma unroll
    for (int c = 0; c < RC; c++) {
        float mv = mean_sigma[c], sv = sig_sigma[c];
        uni = uni && (mv == ms0) && (sv == ms0);
        maxls = fmaxf(maxls, fmaxf(mv, sv));
    }

    float smax = __expf(maxls);
    float dxmax = smax * sqrtf(2.0f * CUT_T);
    int glo, ghi;
    if (dxmax > 4.2f) { glo = 0; ghi = GG - 1; }
    else {
        glo = max(0, (int)((xo - XMINF - dxmax) / STEPF));
        ghi = min(GG - 1, (int)((xo - XMINF + dxmax) / STEPF) + 1);
    }

    float pm[RC], ps[RC];
    if (uni) {
        float s = __expf(ms0);
        float coef = -0.5f / (s * s);
        unsigned long long pmP[4] = {0ull, 0ull, 0ull, 0ull};
        for (int g = glo + lane8; g <= ghi; g += 8) {
            float gv = XMINF + (float)g * STEPF;
            float dd = gv - xo; dd *= dd;
            float e = __expf(coef * dd);
            unsigned long long ee;
            PACK_F32X2(ee, e, e);
            ulonglong2 h01 = *(const ulonglong2*)&h_sh[g * RC];
            ulonglong2 h23 = *(const ulonglong2*)&h_sh[g * RC + 4];
            FMA_F32X2(pmP[0], ee, h01.x, pmP[0]);
            FMA_F32X2(pmP[1], ee, h01.y, pmP[1]);
            FMA_F32X2(pmP[2], ee, h23.x, pmP[2]);
            FMA_F32X2(pmP[3], ee, h23.y, pmP[3]);
        }
        #pragma unroll
        for (int j = 0; j < 4; j++)
            UNPACK_F32X2(pm[2 * j], pm[2 * j + 1], pmP[j]);
        #pragma unroll
        for (int c = 0; c < RC; c++) {
            #pragma unroll
            for (int off = 4; off; off >>= 1)
                pm[c] += __shfl_xor_sync(0xffffffffu, pm[c], off);
            ps[c] = pm[c];
        }
    } else {
        float mc[RC], scf[RC];
        #pragma unroll
        for (int c = 0; c < RC; c++) {
            float s = __expf(mean_sigma[c]); mc[c]  = -0.5f / (s * s);
            s       = __expf(sig_sigma[c]);  scf[c] = -0.5f / (s * s);
            pm[c] = 0.f; ps[c] = 0.f;
        }
        for (int g = glo + lane8; g <= ghi; g += 8) {
            float gv = XMINF + (float)g * STEPF;
            float dd = gv - xo; dd *= dd;
            #pragma unroll
            for (int c = 0; c < RC; c++) {
                float hv = h_sh[g * RC + c];
                pm[c] += hv * __expf(mc[c]  * dd);
                ps[c] += hv * __expf(scf[c] * dd);
            }
        }
        #pragma unroll
        for (int c = 0; c < RC; c++) {
            #pragma unroll
            for (int off = 4; off; off >>= 1) {
                pm[c] += __shfl_xor_sync(0xffffffffu, pm[c], off);
                ps[c] += __shfl_xor_sync(0xffffffffu, ps[c], off);
            }
        }
    }

    size_t base = (size_t)(b * MM + m) * RC;
    {
        int c = lane8;
        g_P[base + c] = ps[c];
        float qc = 0.f;
        #pragma unroll
        for (int j = 0; j < RC; j++) qc = fmaf(g_G[c * RC + j], ps[j], qc);
        g_Q[base + c] = qc;
    }
    if (lane8 == 0) {
        float uacc = 0.5f * g_s[0];
        #pragma unroll
        for (int c = 0; c < RC; c++) uacc = fmaf(ps[c], g_wb[c], uacc);
        g_u[b * MM + m] = uacc;
    } else if (lane8 == 1) {
        float mv = mean_b[0];
        #pragma unroll
        for (int c = 0; c < RC; c++) mv = fmaf(pm[c], mean_W[c], mv);
        mean_out[b * MM + m] = mv;
    }
}

// =====================================================================
// Kernel D: cov = Q.P + u[m] + u[n]  (+noise diag)   [s folded into u]
// 64x64 tile / block, 256 threads (16x16), 4x4 per thread, f32x2.
// Q duplicated {q,q} in smem; P k-major. (Measured ~30us config.)
// =====================================================================
__global__ void __launch_bounds__(256) cov_kernel(
    float* __restrict__ cov, const float* __restrict__ noise_scale)
{
    int b  = blockIdx.y;
    int tm = blockIdx.x >> 5;
    int tn = blockIdx.x & 31;

    __shared__ float QsD[RC][128];     // [k][2*m] duplicated pairs {q,q}
    __shared__ float PsT[RC][64];      // [k][m]
    __shared__ float UmS[64], UnS[64];

    int tid = threadIdx.x;
    int rowBase = tm * 64, colBase = tn * 64;

    if (tid < 128) {
        int r = tid >> 1, q4 = (tid & 1) * 4;
        float4 v = *(const float4*)(g_Q + (size_t)(b * MM + rowBase + r) * RC + q4);
        *(float2*)&QsD[q4 + 0][2 * r] = make_float2(v.x, v.x);
        *(float2*)&QsD[q4 + 1][2 * r] = make_float2(v.y, v.y);
        *(float2*)&QsD[q4 + 2][2 * r] = make_float2(v.z, v.z);
        *(float2*)&QsD[q4 + 3][2 * r] = make_float2(v.w, v.w);
    } else {
        int t = tid - 128;
        int r = t >> 1, q4 = (t & 1) * 4;
        float4 v = *(const float4*)(g_P + (size_t)(b * MM + colBase + r) * RC + q4);
        PsT[q4 + 0][r] = v.x;
        PsT[q4 + 1][r] = v.y;
        PsT[q4 + 2][r] = v.z;
        PsT[q4 + 3][r] = v.w;
    }
    if (tid < 64)       UmS[tid]      = g_u[b * MM + rowBase + tid];
    else if (tid < 128) UnS[tid - 64] = g_u[b * MM + colBase + tid - 64];
    __syncthreads();

    int tx = tid & 15, ty = tid >> 4;

    unsigned long long acc[4][2];
    #pragma unroll
    for (int i = 0; i < 4; i++) { acc[i][0] = 0ull; acc[i][1] = 0ull; }

    #pragma unroll
    for (int k = 0; k < RC; k++) {
        ulonglong2 qq01 = *(const ulonglong2*)&QsD[k][8 * ty];
        ulonglong2 qq23 = *(const ulonglong2*)&QsD[k][8 * ty + 4];
        ulonglong2 pp   = *(const ulonglong2*)&PsT[k][4 * tx];

        FMA_F32X2(acc[0][0], qq01.x, pp.x, acc[0][0]);
        FMA_F32X2(acc[0][1], qq01.x, pp.y, acc[0][1]);
        FMA_F32X2(acc[1][0], qq01.y, pp.x, acc[1][0]);
        FMA_F32X2(acc[1][1], qq01.y, pp.y, acc[1][1]);
        FMA_F32X2(acc[2][0], qq23.x, pp.x, acc[2][0]);
        FMA_F32X2(acc[2][1], qq23.x, pp.y, acc[2][1]);
        FMA_F32X2(acc[3][0], qq23.y, pp.x, acc[3][0]);
        FMA_F32X2(acc[3][1], qq23.y, pp.y, acc[3][1]);
    }

    float noisev = __expf(noise_scale[0]);
    bool diag = (tm == tn) && (tx == ty);

    float un0 = UnS[tx * 4 + 0], un1 = UnS[tx * 4 + 1];
    float un2 = UnS[tx * 4 + 2], un3 = UnS[tx * 4 + 3];

    float* C = cov + (size_t)b * MM * MM;
    #pragma unroll
    for (int i = 0; i < 4; i++) {
        float ums = UmS[ty * 4 + i];
        float o0, o1, o2, o3;
        UNPACK_F32X2(o0, o1, acc[i][0]);
        UNPACK_F32X2(o2, o3, acc[i][1]);
        o0 += ums + un0; o1 += ums + un1;
        o2 += ums + un2; o3 += ums + un3;
        if (diag) {
            if (i == 0) o0 += noisev;
            if (i == 1) o1 += noisev;
            if (i == 2) o2 += noisev;
            if (i == 3) o3 += noisev;
        }
        int r = rowBase + ty * 4 + i;
        *(float4*)(C + (size_t)r * MM + colBase + tx * 4) =
            make_float4(o0, o1, o2, o3);
    }
}

// =====================================================================
// launch
// =====================================================================
extern "C" void kernel_launch(void* const* d_in, const int* in_sizes, int n_in,
                              void* d_out, int out_size)
{
    const float* x          = (const float*)d_in[0];
    const float* y          = (const float*)d_in[1];
    const float* x_out      = (const float*)d_in[2];
    const float* enc_sigma  = (const float*)d_in[3];
    const float* enc_W      = (const float*)d_in[4];
    const float* enc_b      = (const float*)d_in[5];
    const float* rho_W      = (const float*)d_in[6];
    const float* rho_b      = (const float*)d_in[7];
    const float* mean_sigma = (const float*)d_in[8];
    const float* mean_W     = (const float*)d_in[9];
    const float* mean_b     = (const float*)d_in[10];
    const float* sig_sigma  = (const float*)d_in[11];
    const float* sig_W      = (const float*)d_in[12];
    const float* sig_b      = (const float*)d_in[13];
    const float* noise      = (const float*)d_in[14];

    float* out      = (float*)d_out;
    float* mean_out = out;                    // (8, 2048, 1)
    float* cov_out  = out + BB * MM;          // (8, 2048, 2048)

    encode_kernel<<<BB + 1, 544>>>(x, y, enc_sigma, enc_W, enc_b,
                                   rho_W, rho_b, sig_W, sig_b);

    project_kernel<<<BB * 32, 512>>>(x_out, mean_sigma, mean_W, mean_b,
                                     sig_sigma, mean_out);

    dim3 cgrid(1024, BB);   // 32x32 tiles of 64x64
    cov_kernel<<<cgrid, 256>>>(cov_out, noise);
}

// round 17
// speedup vs baseline: 1.9670x; 1.9670x over previous
#include <cuda_runtime.h>
#include <math.h>

// ---------------- problem constants ----------------
#define BB   8
#define NN   2048
#define MM   2048
#define GG   544          // NUM_GRID
#define RC   8            // RHO_C
#define SC   1024         // SIGMA_CH
#define XMINF (-2.1f)
#define STEPF ((float)(4.2 / 543.0))
#define CUT_T 25.0f       // exp threshold: drop terms below e^-25 of peak

// ---------------- scratch (device globals) ----------------
__device__ float g_h[BB * GG * RC];          // h: [b][g][c]
__device__ float g_P[BB * MM * RC];          // ps[b,m,c]
__device__ float g_Q[BB * MM * RC];          // (G @ ps)[b,m,c]
__device__ float g_u[BB * MM];               // ps . (W b) + s/2
__device__ float g_G[RC * RC];               // sig_W sig_W^T
__device__ float g_wb[RC];                   // sig_W @ sig_b
__device__ float g_s[1];                     // sig_b . sig_b
__device__ float g_xs[BB * NN];              // bucket-sorted x
__device__ float g_ys[BB * NN];              // bucket-sorted y
__device__ int   g_start[BB * (GG + 1)];     // bucket starts per batch

// ---------------- packed f32x2 helpers (Blackwell) ----------------
#define FMA_F32X2(d, a, b, c) \
    asm("fma.rn.f32x2 %0, %1, %2, %3;" : "=l"(d) : "l"(a), "l"(b), "l"(c))
#define UNPACK_F32X2(lo, hi, v) \
    asm("mov.b64 {%0, %1}, %2;" : "=f"(lo), "=f"(hi) : "l"(v))
#define PACK_F32X2(out, lo, hi) \
    asm("mov.b64 %0, {%1, %2};" : "=l"(out) : "f"(lo), "f"(hi))

// window half-width in grid cells for gaussian coef magnitude
__device__ __forceinline__ int windowW(float negc)
{
    float dxmax = sqrtf(CUT_T / fmaxf(negc, 1e-30f));
    float wf = dxmax / STEPF + 2.0f;
    return (wf > (float)GG) ? GG : (int)wf;
}

// =====================================================================
// Kernel A: bucket sort per batch (blocks 0..7) + gram (block 8).
// =====================================================================
__global__ void __launch_bounds__(544) bucket_kernel(
    const float* __restrict__ x, const float* __restrict__ y,
    const float* __restrict__ sig_W, const float* __restrict__ sig_b)
{
    int tid = threadIdx.x;
    int warp = tid >> 5, lane = tid & 31;

    if (blockIdx.x == BB) {
        if (warp < 8) {
            for (int p = warp * 8; p < warp * 8 + 8; p++) {
                int i = p >> 3, j = p & 7;
                float acc = 0.f;
                for (int k = lane; k < SC; k += 32)
                    acc += sig_W[i * SC + k] * sig_W[j * SC + k];
                for (int off = 16; off; off >>= 1)
                    acc += __shfl_xor_sync(0xffffffffu, acc, off);
                if (lane == 0) g_G[p] = acc;
            }
            float acc = 0.f;
            for (int k = lane; k < SC; k += 32)
                acc += sig_W[warp * SC + k] * sig_b[k];
            for (int off = 16; off; off >>= 1)
                acc += __shfl_xor_sync(0xffffffffu, acc, off);
            if (lane == 0) g_wb[warp] = acc;
            if (warp == 0) {
                float a2 = 0.f;
                for (int k = lane; k < SC; k += 32)
                    a2 += sig_b[k] * sig_b[k];
                for (int off = 16; off; off >>= 1)
                    a2 += __shfl_xor_sync(0xffffffffu, a2, off);
                if (lane == 0) g_s[0] = a2;
            }
        }
        return;
    }

    int b = blockIdx.x;
    __shared__ int cnt[GG];
    __shared__ int ofs[GG];
    __shared__ int wsum[17];

    for (int i = tid; i < GG; i += 544) cnt[i] = 0;
    __syncthreads();

    float px[4], py[4];
    int pc[4], np = 0;
    for (int n = tid; n < NN; n += 544) {
        float xv = x[b * NN + n], yv = y[b * NN + n];
        float cf = (xv - XMINF) / STEPF + 0.5f;
        int cell = (int)cf;
        cell = min(max(cell, 0), GG - 1);
        px[np] = xv; py[np] = yv; pc[np] = cell; np++;
        atomicAdd(&cnt[cell], 1);
    }
    __syncthreads();

    int c0 = cnt[tid];
    int v = c0;
    #pragma unroll
    for (int off = 1; off < 32; off <<= 1) {
        int t = __shfl_up_sync(0xffffffffu, v, off);
        if (lane >= off) v += t;
    }
    if (lane == 31) wsum[warp] = v;
    __syncthreads();
    if (warp == 0) {
        int s = (lane < 17) ? wsum[lane] : 0;
        #pragma unroll
        for (int off = 1; off < 32; off <<= 1) {
            int t = __shfl_up_sync(0xffffffffu, s, off);
            if (lane >= off) s += t;
        }
        if (lane < 17) wsum[lane] = s;
    }
    __syncthreads();
    int excl = v - c0 + (warp ? wsum[warp - 1] : 0);
    ofs[tid] = excl;
    g_start[b * (GG + 1) + tid] = excl;
    if (tid == GG - 1) g_start[b * (GG + 1) + GG] = excl + c0;
    __syncthreads();

    for (int i = 0; i < np; i++) {
        int pos = atomicAdd(&ofs[pc[i]], 1);
        g_xs[b * NN + pos] = px[i];
        g_ys[b * NN + pos] = py[i];
    }
}

// =====================================================================
// Kernel B: encode.  One WARP per (b,g), windowed over bucketed points.
// =====================================================================
__global__ void __launch_bounds__(256) encode_kernel(
    const float* __restrict__ enc_sigma, const float* __restrict__ enc_W,
    const float* __restrict__ enc_b, const float* __restrict__ rho_W,
    const float* __restrict__ rho_b)
{
    int warp = threadIdx.x >> 5, lane = threadIdx.x & 31;
    int bg = blockIdx.x * 8 + warp;
    int b  = bg / GG;
    int g  = bg % GG;
    float gv = XMINF + (float)g * STEPF;

    float es0 = enc_sigma[0], es1 = enc_sigma[1];
    float s0 = __expf(es0);  float c0 = -0.5f / (s0 * s0);
    bool same = (es0 == es1);
    float c1 = c0;
    int W = windowW(-c0);
    if (!same) {
        float s1 = __expf(es1);
        c1 = -0.5f / (s1 * s1);
        W = max(W, windowW(-c1));
    }
    int glo = max(0, g - W), ghi = min(GG - 1, g + W);
    int lo = g_start[b * (GG + 1) + glo];
    int hi = g_start[b * (GG + 1) + ghi + 1];

    float f0 = 0.f, f1 = 0.f;
    if (same) {
        for (int n = lo + lane; n < hi; n += 32) {
            float dx = g_xs[b * NN + n] - gv;
            float e  = __expf(c0 * dx * dx);
            f0 += e;
            f1 += g_ys[b * NN + n] * e;
        }
    } else {
        for (int n = lo + lane; n < hi; n += 32) {
            float dx = g_xs[b * NN + n] - gv;
            float d  = dx * dx;
            f0 += __expf(c0 * d);
            f1 += g_ys[b * NN + n] * __expf(c1 * d);
        }
    }
    for (int off = 16; off; off >>= 1) {
        f0 += __shfl_xor_sync(0xffffffffu, f0, off);
        f1 += __shfl_xor_sync(0xffffffffu, f1, off);
    }
    float F0 = f0;
    float F1 = f1 / (f0 + 1e-8f);

    float hh[RC];
    #pragma unroll
    for (int c = 0; c < RC; c++) {
        float z = F0 * enc_W[c] + F1 * enc_W[RC + c] + enc_b[c];
        hh[c] = 1.f / (1.f + __expf(-z));
    }
    if (lane < RC) {
        int c = lane;
        float acc = rho_b[c];
        #pragma unroll
        for (int j = 0; j < RC; j++) acc += hh[j] * rho_W[j * RC + c];
        g_h[(b * GG + g) * RC + c] = acc;   // [b][g][c]
    }
}

// =====================================================================
// Kernel C: project.  One 8-lane GROUP per (b,m); 64 m per block (512T).
// g_u gets +s/2 folded in (cov adds u[m]+u[n] -> +s total).
// =====================================================================
__global__ void __launch_bounds__(512) project_kernel(
    const float* __restrict__ x_out,
    const float* __restrict__ mean_sigma, const float* __restrict__ mean_W,
    const float* __restrict__ mean_b,
    const float* __restrict__ sig_sigma,
    float* __restrict__ mean_out)
{
    __shared__ __align__(16) float h_sh[GG * RC];    // [g][c]

    int b  = blockIdx.x >> 5;          // 32 blocks per batch
    int m0 = (blockIdx.x & 31) * 64;
    int tid = threadIdx.x;

    for (int i = tid; i < GG * RC; i += 512)
        h_sh[i] = g_h[b * GG * RC + i];
    __syncthreads();

    int gid   = tid >> 3;              // 0..63
    int lane8 = tid & 7;
    int m = m0 + gid;
    float xo = x_out[b * MM + m];

    bool uni = true;
    float ms0 = mean_sigma[0];
    float maxls = ms0;
    #pragma unroll
    for (int c = 0; c < RC; c++) {
        float mv = mean_sigma[c], sv = sig_sigma[c];
        uni = uni && (mv == ms0) && (sv == ms0);
        maxls = fmaxf(maxls, fmaxf(mv, sv));
    }

    float smax = __expf(maxls);
    float dxmax = smax * sqrtf(2.0f * CUT_T);
    int glo, ghi;
    if (dxmax > 4.2f) { glo = 0; ghi = GG - 1; }
    else {
        glo = max(0, (int)((xo - XMINF - dxmax) / STEPF));
        ghi = min(GG - 1, (int)((xo - XMINF + dxmax) / STEPF) + 1);
    }

    float pm[RC], ps[RC];
    if (uni) {
        float s = __expf(ms0);
        float coef = -0.5f / (s * s);
        unsigned long long pmP[4] = {0ull, 0ull, 0ull, 0ull};
        for (int g = glo + lane8; g <= ghi; g += 8) {
            float gv = XMINF + (float)g * STEPF;
            float dd = gv - xo; dd *= dd;
            float e = __expf(coef * dd);
            unsigned long long ee;
            PACK_F32X2(ee, e, e);
            ulonglong2 h01 = *(const ulonglong2*)&h_sh[g * RC];
            ulonglong2 h23 = *(const ulonglong2*)&h_sh[g * RC + 4];
            FMA_F32X2(pmP[0], ee, h01.x, pmP[0]);
            FMA_F32X2(pmP[1], ee, h01.y, pmP[1]);
            FMA_F32X2(pmP[2], ee, h23.x, pmP[2]);
            FMA_F32X2(pmP[3], ee, h23.y, pmP[3]);
        }
        #pragma unroll
        for (int j = 0; j < 4; j++)
            UNPACK_F32X2(pm[2 * j], pm[2 * j + 1], pmP[j]);
        #pragma unroll
        for (int c = 0; c < RC; c++) {
            #pragma unroll
            for (int off = 4; off; off >>= 1)
                pm[c] += __shfl_xor_sync(0xffffffffu, pm[c], off);
            ps[c] = pm[c];
        }
    } else {
        float mc[RC], scf[RC];
        #pragma unroll
        for (int c = 0; c < RC; c++) {
            float s = __expf(mean_sigma[c]); mc[c]  = -0.5f / (s * s);
            s       = __expf(sig_sigma[c]);  scf[c] = -0.5f / (s * s);
            pm[c] = 0.f; ps[c] = 0.f;
        }
        for (int g = glo + lane8; g <= ghi; g += 8) {
            float gv = XMINF + (float)g * STEPF;
            float dd = gv - xo; dd *= dd;
            #pragma unroll
            for (int c = 0; c < RC; c++) {
                float hv = h_sh[g * RC + c];
                pm[c] += hv * __expf(mc[c]  * dd);
                ps[c] += hv * __expf(scf[c] * dd);
            }
        }
        #pragma unroll
        for (int c = 0; c < RC; c++) {
            #pragma unroll
            for (int off = 4; off; off >>= 1) {
                pm[c] += __shfl_xor_sync(0xffffffffu, pm[c], off);
                ps[c] += __shfl_xor_sync(0xffffffffu, ps[c], off);
            }
        }
    }

    size_t base = (size_t)(b * MM + m) * RC;
    {
        int c = lane8;
        g_P[base + c] = ps[c];
        float qc = 0.f;
        #pragma unroll
        for (int j = 0; j < RC; j++) qc = fmaf(g_G[c * RC + j], ps[j], qc);
        g_Q[base + c] = qc;
    }
    if (lane8 == 0) {
        float uacc = 0.5f * g_s[0];
        #pragma unroll
        for (int c = 0; c < RC; c++) uacc = fmaf(ps[c], g_wb[c], uacc);
        g_u[b * MM + m] = uacc;
    } else if (lane8 == 1) {
        float mv = mean_b[0];
        #pragma unroll
        for (int c = 0; c < RC; c++) mv = fmaf(pm[c], mean_W[c], mv);
        mean_out[b * MM + m] = mv;
    }
}

// =====================================================================
// Kernel D: cov = Q.P + u[m] + u[n]  (+noise diag)   [s folded into u]
// 64x64 tile / block, 256 threads (16x16), 4x4 per thread, f32x2.
// Q duplicated {q,q} in smem; P k-major. (Measured ~30.4us config.)
// =====================================================================
__global__ void __launch_bounds__(256) cov_kernel(
    float* __restrict__ cov, const float* __restrict__ noise_scale)
{
    int b  = blockIdx.y;
    int tm = blockIdx.x >> 5;
    int tn = blockIdx.x & 31;

    __shared__ float QsD[RC][128];     // [k][2*m] duplicated pairs {q,q}
    __shared__ float PsT[RC][64];      // [k][m]
    __shared__ float UmS[64], UnS[64];

    int tid = threadIdx.x;
    int rowBase = tm * 64, colBase = tn * 64;

    if (tid < 128) {
        int r = tid >> 1, q4 = (tid & 1) * 4;
        float4 v = *(const float4*)(g_Q + (size_t)(b * MM + rowBase + r) * RC + q4);
        *(float2*)&QsD[q4 + 0][2 * r] = make_float2(v.x, v.x);
        *(float2*)&QsD[q4 + 1][2 * r] = make_float2(v.y, v.y);
        *(float2*)&QsD[q4 + 2][2 * r] = make_float2(v.z, v.z);
        *(float2*)&QsD[q4 + 3][2 * r] = make_float2(v.w, v.w);
    } else {
        int t = tid - 128;
        int r = t >> 1, q4 = (t & 1) * 4;
        float4 v = *(const float4*)(g_P + (size_t)(b * MM + colBase + r) * RC + q4);
        PsT[q4 + 0][r] = v.x;
        PsT[q4 + 1][r] = v.y;
        PsT[q4 + 2][r] = v.z;
        PsT[q4 + 3][r] = v.w;
    }
    if (tid < 64)       UmS[tid]      = g_u[b * MM + rowBase + tid];
    else if (tid < 128) UnS[tid - 64] = g_u[b * MM + colBase + tid - 64];
    __syncthreads();

    int tx = tid & 15, ty = tid >> 4;

    unsigned long long acc[4][2];
    #pragma unroll
    for (int i = 0; i < 4; i++) { acc[i][0] = 0ull; acc[i][1] = 0ull; }

    #pragma unroll
    for (int k = 0; k < RC; k++) {
        ulonglong2 qq01 = *(const ulonglong2*)&QsD[k][8 * ty];
        ulonglong2 qq23 = *(const ulonglong2*)&QsD[k][8 * ty + 4];
        ulonglong2 pp   = *(const ulonglong2*)&PsT[k][4 * tx];

        FMA_F32X2(acc[0][0], qq01.x, pp.x, acc[0][0]);
        FMA_F32X2(acc[0][1], qq01.x, pp.y, acc[0][1]);
        FMA_F32X2(acc[1][0], qq01.y, pp.x, acc[1][0]);
        FMA_F32X2(acc[1][1], qq01.y, pp.y, acc[1][1]);
        FMA_F32X2(acc[2][0], qq23.x, pp.x, acc[2][0]);
        FMA_F32X2(acc[2][1], qq23.x, pp.y, acc[2][1]);
        FMA_F32X2(acc[3][0], qq23.y, pp.x, acc[3][0]);
        FMA_F32X2(acc[3][1], qq23.y, pp.y, acc[3][1]);
    }

    float noisev = __expf(noise_scale[0]);
    bool diag = (tm == tn) && (tx == ty);

    float un0 = UnS[tx * 4 + 0], un1 = UnS[tx * 4 + 1];
    float un2 = UnS[tx * 4 + 2], un3 = UnS[tx * 4 + 3];

    float* C = cov + (size_t)b * MM * MM;
    #pragma unroll
    for (int i = 0; i < 4; i++) {
        float ums = UmS[ty * 4 + i];
        float o0, o1, o2, o3;
        UNPACK_F32X2(o0, o1, acc[i][0]);
        UNPACK_F32X2(o2, o3, acc[i][1]);
        o0 += ums + un0; o1 += ums + un1;
        o2 += ums + un2; o3 += ums + un3;
        if (diag) {
            if (i == 0) o0 += noisev;
            if (i == 1) o1 += noisev;
            if (i == 2) o2 += noisev;
            if (i == 3) o3 += noisev;
        }
        int r = rowBase + ty * 4 + i;
        *(float4*)(C + (size_t)r * MM + colBase + tx * 4) =
            make_float4(o0, o1, o2, o3);
    }
}

// =====================================================================
// launch
// =====================================================================
extern "C" void kernel_launch(void* const* d_in, const int* in_sizes, int n_in,
                              void* d_out, int out_size)
{
    const float* x          = (const float*)d_in[0];
    const float* y          = (const float*)d_in[1];
    const float* x_out      = (const float*)d_in[2];
    const float* enc_sigma  = (const float*)d_in[3];
    const float* enc_W      = (const float*)d_in[4];
    const float* enc_b      = (const float*)d_in[5];
    const float* rho_W      = (const float*)d_in[6];
    const float* rho_b      = (const float*)d_in[7];
    const float* mean_sigma = (const float*)d_in[8];
    const float* mean_W     = (const float*)d_in[9];
    const float* mean_b     = (const float*)d_in[10];
    const float* sig_sigma  = (const float*)d_in[11];
    const float* sig_W      = (const float*)d_in[12];
    const float* sig_b      = (const float*)d_in[13];
    const float* noise      = (const float*)d_in[14];

    float* out      = (float*)d_out;
    float* mean_out = out;                    // (8, 2048, 1)
    float* cov_out  = out + BB * MM;          // (8, 2048, 2048)

    bucket_kernel<<<BB + 1, 544>>>(x, y, sig_W, sig_b);

    encode_kernel<<<BB * GG / 8, 256>>>(enc_sigma, enc_W, enc_b, rho_W, rho_b);

    project_kernel<<<BB * 32, 512>>>(x_out, mean_sigma, mean_W, mean_b,
                                     sig_sigma, mean_out);

    dim3 cgrid(1024, BB);   // 32x32 tiles of 64x64
    cov_kernel<<<cgrid, 256>>>(cov_out, noise);
}